// round 6
// baseline (speedup 1.0000x reference)
#include <cuda_runtime.h>
#include <cuda_bf16.h>
#include <cstdint>

// DGCRM: after dead-code elimination, output = GRU cell over 16384 rows:
//   c = [h(64), x(2)]  (permuted combined vector, 66 wide)
//   z = sigmoid(c @ Wz + bz); r = sigmoid(c @ Wr + br)
//   cand = [r*h, x];  hc = tanh(cand @ Wc + bc)
//   out = z*h + (1-z)*hc
// Wz/Wr/Wc are folds of rnn_W pairs (reference GConv_RNN bug makes diffusion
// terms no-ops: concat([inp, .05*inp, .05*inp]) @ W).
//
// R3 -> R4: occupancy was the binding constraint (occ 12.4%, issue 25%).
// 32 rows/CTA, grid=512, 3 CTAs/SM (smem 60KB), weights pre-permuted +
// pre-packed for direct f32x2 operands, warp-local syncs between GEMM phases.

#define CIN 66
#define HIDD 64
#define RPB 32
#define TPB 256

__device__ float g_Wf[3 * CIN * HIDD];   // permuted rows: [h0..h63, x0, x1]
__device__ float g_Bf[3 * HIDD];

__device__ __forceinline__ unsigned long long pk2(float a, float b) {
    unsigned long long r;
    asm("mov.b64 %0, {%1, %2};" : "=l"(r) : "f"(a), "f"(b));
    return r;
}
__device__ __forceinline__ void upk2(unsigned long long v, float& a, float& b) {
    asm("mov.b64 {%0, %1}, %2;" : "=f"(a), "=f"(b) : "l"(v));
}
__device__ __forceinline__ void fma2(unsigned long long& d, unsigned long long a, unsigned long long b) {
    asm("fma.rn.f32x2 %0, %1, %2, %0;" : "+l"(d) : "l"(a), "l"(b));
}
__device__ __forceinline__ float fsig(float v) { return 1.f / (1.f + __expf(-v)); }
__device__ __forceinline__ float ftanh(float v) { return 1.f - 2.f / (__expf(2.f * v) + 1.f); }

// Fold rnn_W[6,198,64] -> 3 effective [66,64] matrices + biases, with the
// row permutation applied here (combined order [x,h] -> stored order [h,x]):
//   g_Wf[m][j] = Weff[m][ j<64 ? j+2 : j-64 ]
__global__ void fold_kernel(const float* __restrict__ W, const float* __restrict__ bvec) {
    int idx = blockIdx.x * blockDim.x + threadIdx.x;
    if (idx < 3 * CIN * HIDD) {
        int m = idx / (CIN * HIDD);
        int rem = idx - m * (CIN * HIDD);
        int j = rem / HIDD;
        int col = rem - j * HIDD;
        int k = (j < HIDD) ? (j + 2) : (j - HIDD);   // source combined row
        float s = 0.f;
#pragma unroll
        for (int t = 0; t < 2; ++t) {
            const float* base = W + (size_t)(2 * m + t) * 198 * HIDD + col;
            s += base[(size_t)k * HIDD]
               + 0.05f * (base[(size_t)(66 + k) * HIDD] + base[(size_t)(132 + k) * HIDD]);
        }
        g_Wf[idx] = s;
    }
    if (idx < 3 * HIDD) {
        int m = idx / HIDD, j = idx - m * HIDD;
        g_Bf[idx] = bvec[(2 * m) * HIDD + j] + bvec[(2 * m + 1) * HIDD + j];
    }
}

// Main fused GRU kernel. Block: 32 rows x 64 cols, 256 threads.
// Thread: 2 rows x 4 cols. smem: Wsm[3][66][64], Bsm[3][64], As[32][68].
__global__ void __launch_bounds__(TPB, 3) dgcrm_main(
    const float* __restrict__ x, const float* __restrict__ h0, float* __restrict__ out)
{
    extern __shared__ float sm[];
    float* Wsm = sm;                        // 12672 floats
    float* Bsm = Wsm + 3 * CIN * HIDD;      // 192
    float* As  = Bsm + 3 * HIDD;            // 32*68 = 2176

    const int tid = threadIdx.x;
    const int tx = tid & 15;                // col group (4 cols)
    const int ty = tid >> 4;                // row group (2 rows)
    const int rowbase = ty * 2;
    const int g0 = blockIdx.x * RPB;

    // Stage weights (already permuted+folded): straight float4 copy.
    for (int i = tid; i < 3 * CIN * 16; i += TPB) {
        float4 v = *(const float4*)(g_Wf + (size_t)i * 4);
        *(float4*)(Wsm + (size_t)i * 4) = v;
    }
    if (tid < 3 * HIDD) Bsm[tid] = g_Bf[tid];

    // A tile: hidden into As[:,0:64], x into As[:,64:66].
    for (int i = tid; i < RPB * 16; i += TPB) {
        int r = i >> 4, c = i & 15;
        float4 v = *(const float4*)(h0 + (size_t)(g0 + r) * HIDD + c * 4);
        *(float4*)(As + r * 68 + c * 4) = v;
    }
    if (tid < RPB) {
        float2 v = *(const float2*)(x + (size_t)(g0 + tid) * 2);
        As[tid * 68 + 64] = v.x;
        As[tid * 68 + 65] = v.y;
    }
    __syncthreads();

    const ulonglong2* Wz2 = (const ulonglong2*)Wsm;
    const ulonglong2* Wr2 = (const ulonglong2*)(Wsm + CIN * HIDD);
    const ulonglong2* Wc2 = (const ulonglong2*)(Wsm + 2 * CIN * HIDD);
    const float* arow = As + rowbase * 68;

    unsigned long long zacc[2][2], racc[2][2];
#pragma unroll
    for (int rr = 0; rr < 2; rr++) {
        zacc[rr][0] = 0ull; zacc[rr][1] = 0ull;
        racc[rr][0] = 0ull; racc[rr][1] = 0ull;
    }

    // ---- z / r GEMM phase ----
#pragma unroll 6
    for (int j = 0; j < CIN; ++j) {
        const ulonglong2 bz = Wz2[j * 16 + tx];
        const ulonglong2 br = Wr2[j * 16 + tx];
        const float a0 = arow[j];
        const float a1 = arow[68 + j];
        const unsigned long long a0p = pk2(a0, a0);
        const unsigned long long a1p = pk2(a1, a1);
        fma2(zacc[0][0], a0p, bz.x); fma2(zacc[0][1], a0p, bz.y);
        fma2(racc[0][0], a0p, br.x); fma2(racc[0][1], a0p, br.y);
        fma2(zacc[1][0], a1p, bz.x); fma2(zacc[1][1], a1p, bz.y);
        fma2(racc[1][0], a1p, br.x); fma2(racc[1][1], a1p, br.y);
    }
    // Rows (2ty,2ty+1) are read/written only by the 16 threads sharing ty
    // (one half-warp) -> warp-level sync suffices between phases.
    __syncwarp();

    // ---- candidate: As[row][col] = sigmoid(r+br) * h, save h ----
    float4 hsv[2];
    const float4 brb = *(const float4*)(Bsm + HIDD + tx * 4);
#pragma unroll
    for (int rr = 0; rr < 2; rr++) {
        float* ap = As + (rowbase + rr) * 68 + tx * 4;
        float4 h4 = *(const float4*)ap;
        hsv[rr] = h4;
        float r0, r1, r2, r3;
        upk2(racc[rr][0], r0, r1);
        upk2(racc[rr][1], r2, r3);
        float4 c4;
        c4.x = fsig(r0 + brb.x) * h4.x;
        c4.y = fsig(r1 + brb.y) * h4.y;
        c4.z = fsig(r2 + brb.z) * h4.z;
        c4.w = fsig(r3 + brb.w) * h4.w;
        *(float4*)ap = c4;
    }
    __syncwarp();

    // ---- hc GEMM phase ----
    unsigned long long cacc[2][2];
    cacc[0][0] = cacc[0][1] = cacc[1][0] = cacc[1][1] = 0ull;
#pragma unroll 6
    for (int j = 0; j < CIN; ++j) {
        const ulonglong2 bc = Wc2[j * 16 + tx];
        const float a0 = arow[j];
        const float a1 = arow[68 + j];
        const unsigned long long a0p = pk2(a0, a0);
        const unsigned long long a1p = pk2(a1, a1);
        fma2(cacc[0][0], a0p, bc.x); fma2(cacc[0][1], a0p, bc.y);
        fma2(cacc[1][0], a1p, bc.x); fma2(cacc[1][1], a1p, bc.y);
    }

    // ---- epilogue: out = z*h + (1-z)*hc ----
    const float4 bzb = *(const float4*)(Bsm + tx * 4);
    const float4 bcb = *(const float4*)(Bsm + 2 * HIDD + tx * 4);
#pragma unroll
    for (int rr = 0; rr < 2; rr++) {
        float z0, z1, z2, z3, c0, c1, c2, c3;
        upk2(zacc[rr][0], z0, z1); upk2(zacc[rr][1], z2, z3);
        upk2(cacc[rr][0], c0, c1); upk2(cacc[rr][1], c2, c3);
        z0 = fsig(z0 + bzb.x); z1 = fsig(z1 + bzb.y);
        z2 = fsig(z2 + bzb.z); z3 = fsig(z3 + bzb.w);
        c0 = ftanh(c0 + bcb.x); c1 = ftanh(c1 + bcb.y);
        c2 = ftanh(c2 + bcb.z); c3 = ftanh(c3 + bcb.w);
        float4 o;
        o.x = z0 * hsv[rr].x + (1.f - z0) * c0;
        o.y = z1 * hsv[rr].y + (1.f - z1) * c1;
        o.z = z2 * hsv[rr].z + (1.f - z2) * c2;
        o.w = z3 * hsv[rr].w + (1.f - z3) * c3;
        *(float4*)(out + (size_t)(g0 + rowbase + rr) * HIDD + tx * 4) = o;
    }
}

static const int SMEM_BYTES = (3 * CIN * HIDD + 3 * HIDD + RPB * 68) * 4;  // 60160

extern "C" void kernel_launch(void* const* d_in, const int* in_sizes, int n_in,
                              void* d_out, int out_size) {
    (void)in_sizes; (void)n_in; (void)out_size;
    const float* x    = (const float*)d_in[0];    // [16,1024,2]
    const float* h0   = (const float*)d_in[1];    // [16,1024,64]
    const float* rnnW = (const float*)d_in[12];   // [6,198,64]
    const float* rnnb = (const float*)d_in[13];   // [6,64]
    float* out = (float*)d_out;                   // [16,1024,64]

    cudaFuncSetAttribute(dgcrm_main, cudaFuncAttributeMaxDynamicSharedMemorySize, SMEM_BYTES);

    fold_kernel<<<(3 * CIN * HIDD + 255) / 256, 256>>>(rnnW, rnnb);
    dgcrm_main<<<16384 / RPB, TPB, SMEM_BYTES>>>(x, h0, out);
}